// round 1
// baseline (speedup 1.0000x reference)
#include <cuda_runtime.h>
#include <cuda_bf16.h>
#include <cstdint>

// Problem constants (from reference setup_inputs):
//   X: (N=4096, D1=64, L=16) fp32, Y: (4096, 64, 16) fp32, output: scalar fp32.
#define NPTS 4096
#define DDIM 64
#define LSTEPS 16
#define BT 128                 // pair tile (BT x BT)
#define NT (NPTS / BT)         // 32 tile-rows
#define NTILES (NT * (NT + 1) / 2)   // 528 upper-triangular tiles
#define SSTR 132               // padded smem row stride (floats), 16B-aligned, kills STS conflicts
#define SMEM_BYTES (4 * DDIM * SSTR * 4)   // 4 tiles of [64][132] fp32 = 135168 B

// -------- device scratch (no cudaMalloc allowed; zero-init .bss-style globals) --------
__device__ float g_Xt[LSTEPS * NPTS * DDIM];   // 16 MB: X transposed to [l][n][d]
__device__ float g_Yt[LSTEPS * NPTS * DDIM];   // 16 MB
__device__ float g_sqx[LSTEPS * NPTS];
__device__ float g_sqy[LSTEPS * NPTS];
__device__ float g_Sx[LSTEPS * NPTS];          // row sums of Kx per timestep
__device__ float g_Sy[LSTEPS * NPTS];
__device__ float g_A[LSTEPS];                  // sum_ij Kx*Ky per timestep

// ---------------------------------------------------------------------------
// Zero the accumulators (graph replays must start clean).
// ---------------------------------------------------------------------------
__global__ void hsic_zero_kernel() {
    int i = blockIdx.x * 256 + threadIdx.x;
    if (i < LSTEPS * NPTS) { g_Sx[i] = 0.f; g_Sy[i] = 0.f; }
    if (i < LSTEPS) g_A[i] = 0.f;
}

// ---------------------------------------------------------------------------
// Transpose (N,D,L) -> (L,N,D) and compute per-(l,n) squared norms.
// One block handles 4 points (4*1024 floats) through padded smem.
// ---------------------------------------------------------------------------
__global__ void hsic_transpose_kernel(const float* __restrict__ X,
                                      const float* __restrict__ Y) {
    const float* src = blockIdx.y ? Y : X;
    float* dst = blockIdx.y ? g_Yt : g_Xt;
    float* sq  = blockIdx.y ? g_sqy : g_sqx;
    int n0 = blockIdx.x * 4;
    __shared__ float s[4 * LSTEPS * (DDIM + 1)];   // [n][l][64+1]

    // coalesced read: element (n, d, l), l fastest
    #pragma unroll
    for (int it = 0; it < 16; it++) {
        int idx = it * 256 + threadIdx.x;          // 0..4095
        int n = idx >> 10;
        int r = idx & 1023;                        // d*16 + l
        int d = r >> 4, l = r & 15;
        s[n * (LSTEPS * 65) + l * 65 + d] = src[(size_t)(n0 + n) * 1024 + r];
    }
    __syncthreads();
    // coalesced write: (l, n, d), d fastest
    #pragma unroll
    for (int it = 0; it < 16; it++) {
        int idx = it * 256 + threadIdx.x;          // 0..4095
        int l = idx >> 8;
        int n = (idx >> 6) & 3;
        int d = idx & 63;
        dst[(size_t)l * NPTS * DDIM + (size_t)(n0 + n) * DDIM + d] =
            s[n * (LSTEPS * 65) + l * 65 + d];
    }
    // squared norms: 64 (n,l) pairs per block
    if (threadIdx.x < 64) {
        int n = threadIdx.x >> 4, l = threadIdx.x & 15;
        float acc = 0.f;
        #pragma unroll
        for (int d = 0; d < DDIM; d++) {
            float v = s[n * (LSTEPS * 65) + l * 65 + d];
            acc = fmaf(v, v, acc);
        }
        sq[l * NPTS + n0 + n] = acc;
    }
}

// ---------------------------------------------------------------------------
// Main fused kernel: one block = one (l, tile_i <= tile_j) 128x128 pair tile.
// Computes both Gram tiles (fp32 outer-product register tiling, 8x8 per thread),
// applies exp(-d2/2), accumulates sum(Kx*Ky), row sums, col sums.
// ---------------------------------------------------------------------------
__global__ void __launch_bounds__(256, 1) hsic_main_kernel() {
    const int l = blockIdx.y;
    // map linear tile index -> (ti, tj), ti <= tj
    int t = blockIdx.x;
    int ti = 0;
    while (t >= NT - ti) { t -= NT - ti; ti++; }
    const int tj = ti + t;
    const bool diag = (ti == tj);

    extern __shared__ float smem[];
    float* Xi = smem;                       // [64][SSTR]
    float* Xj = smem + DDIM * SSTR;
    float* Yi = smem + 2 * DDIM * SSTR;
    float* Yj = smem + 3 * DDIM * SSTR;
    __shared__ float sdot[8];

    const float* __restrict__ Xt = g_Xt + (size_t)l * NPTS * DDIM;
    const float* __restrict__ Yt = g_Yt + (size_t)l * NPTS * DDIM;
    const int I = ti * BT, J = tj * BT;
    const int tid = threadIdx.x;

    // ---- load 4 tiles, k-major in smem ----
    #pragma unroll
    for (int it = 0; it < 32; it++) {
        int idx = it * 256 + tid;           // 0..8191
        int m = idx >> 6;                   // 0..127
        int k = idx & 63;
        Xi[k * SSTR + m] = Xt[(size_t)(I + m) * DDIM + k];
        Xj[k * SSTR + m] = Xt[(size_t)(J + m) * DDIM + k];
        Yi[k * SSTR + m] = Yt[(size_t)(I + m) * DDIM + k];
        Yj[k * SSTR + m] = Yt[(size_t)(J + m) * DDIM + k];
    }
    __syncthreads();

    // ---- 8x8 register-tile Gram for both X and Y ----
    const int mb = (tid >> 4) << 3;         // row offset within tile
    const int nb = (tid & 15) << 3;         // col offset within tile
    float accx[64], accy[64];
    #pragma unroll
    for (int i = 0; i < 64; i++) { accx[i] = 0.f; accy[i] = 0.f; }

    #pragma unroll 4
    for (int k = 0; k < DDIM; k++) {
        const float* xk = Xi + k * SSTR;
        const float* xjk = Xj + k * SSTR;
        const float* yk = Yi + k * SSTR;
        const float* yjk = Yj + k * SSTR;
        float4 a0 = *(const float4*)(xk + mb);
        float4 a1 = *(const float4*)(xk + mb + 4);
        float4 b0 = *(const float4*)(xjk + nb);
        float4 b1 = *(const float4*)(xjk + nb + 4);
        float4 c0 = *(const float4*)(yk + mb);
        float4 c1 = *(const float4*)(yk + mb + 4);
        float4 d0 = *(const float4*)(yjk + nb);
        float4 d1 = *(const float4*)(yjk + nb + 4);
        float am[8] = {a0.x, a0.y, a0.z, a0.w, a1.x, a1.y, a1.z, a1.w};
        float bn[8] = {b0.x, b0.y, b0.z, b0.w, b1.x, b1.y, b1.z, b1.w};
        float cm[8] = {c0.x, c0.y, c0.z, c0.w, c1.x, c1.y, c1.z, c1.w};
        float dn[8] = {d0.x, d0.y, d0.z, d0.w, d1.x, d1.y, d1.z, d1.w};
        #pragma unroll
        for (int m = 0; m < 8; m++)
            #pragma unroll
            for (int n = 0; n < 8; n++) {
                accx[m * 8 + n] = fmaf(am[m], bn[n], accx[m * 8 + n]);
                accy[m * 8 + n] = fmaf(cm[m], dn[n], accy[m * 8 + n]);
            }
    }

    // ---- epilogue: RBF + reductions (registers only) ----
    float sxi[8], sxj[8], syi[8], syj[8];
    #pragma unroll
    for (int r = 0; r < 8; r++) {
        sxi[r] = g_sqx[l * NPTS + I + mb + r];
        sxj[r] = g_sqx[l * NPTS + J + nb + r];
        syi[r] = g_sqy[l * NPTS + I + mb + r];
        syj[r] = g_sqy[l * NPTS + J + nb + r];
    }
    float dotp = 0.f;
    float rsx[8], csx[8], rsy[8], csy[8];
    #pragma unroll
    for (int r = 0; r < 8; r++) { rsx[r] = 0.f; csx[r] = 0.f; rsy[r] = 0.f; csy[r] = 0.f; }

    #pragma unroll
    for (int m = 0; m < 8; m++) {
        #pragma unroll
        for (int n = 0; n < 8; n++) {
            float d2x = fmaxf(sxi[m] + sxj[n] - 2.f * accx[m * 8 + n], 0.f);
            float d2y = fmaxf(syi[m] + syj[n] - 2.f * accy[m * 8 + n], 0.f);
            float kx = __expf(-0.5f * d2x);
            float ky = __expf(-0.5f * d2y);
            dotp = fmaf(kx, ky, dotp);
            rsx[m] += kx; csx[n] += kx;
            rsy[m] += ky; csy[n] += ky;
        }
    }

    // row sums: reduce across the 16 threads sharing a tile-row (txn = tid&15,
    // which are contiguous 16-lane groups inside a warp -> shfl_xor(<16) stays inside)
    #pragma unroll
    for (int r = 0; r < 8; r++) {
        float vx = rsx[r], vy = rsy[r];
        #pragma unroll
        for (int o = 8; o > 0; o >>= 1) {
            vx += __shfl_xor_sync(0xffffffffu, vx, o);
            vy += __shfl_xor_sync(0xffffffffu, vy, o);
        }
        if ((tid & 15) == 0) {
            atomicAdd(&g_Sx[l * NPTS + I + mb + r], vx);
            atomicAdd(&g_Sy[l * NPTS + I + mb + r], vy);
        }
    }

    // tile-local dot: full-warp reduce, lane 0 holds warp partial
    float v = dotp;
    #pragma unroll
    for (int o = 16; o > 0; o >>= 1) v += __shfl_xor_sync(0xffffffffu, v, o);

    __syncthreads();   // everyone done reading smem tiles; reuse Xi region below

    // stage column partials (needed only for off-diagonal tiles) + warp dots
    float* redx = smem;                    // [128][17]
    float* redy = smem + 128 * 17;         // [128][17]
    const int tym = tid >> 4;
    #pragma unroll
    for (int c = 0; c < 8; c++) {
        redx[(nb + c) * 17 + tym] = csx[c];
        redy[(nb + c) * 17 + tym] = csy[c];
    }
    if ((tid & 31) == 0) sdot[tid >> 5] = v;
    __syncthreads();

    if (tid == 0) {
        float s = 0.f;
        #pragma unroll
        for (int w = 0; w < 8; w++) s += sdot[w];
        atomicAdd(&g_A[l], diag ? s : 2.f * s);
    }
    if (tid < 128 && !diag) {
        float sx = 0.f, sy = 0.f;
        #pragma unroll
        for (int q = 0; q < 16; q++) { sx += redx[tid * 17 + q]; sy += redy[tid * 17 + q]; }
        atomicAdd(&g_Sx[l * NPTS + J + tid], sx);
        atomicAdd(&g_Sy[l * NPTS + J + tid], sy);
    }
}

// ---------------------------------------------------------------------------
// Finalize: total = sum_l ( A_l - (2/n) * sum_i Sx_i Sy_i + Tx*Ty/n^2 ) / (n-1)^2
// ---------------------------------------------------------------------------
__global__ void hsic_finalize_kernel(float* __restrict__ out) {
    __shared__ float sB[512], sTx[512], sTy[512];
    const int tid = threadIdx.x;
    const float n = (float)NPTS;
    float total = 0.f;

    for (int l = 0; l < LSTEPS; l++) {
        float b = 0.f, tx = 0.f, ty = 0.f;
        for (int i = tid; i < NPTS; i += 512) {
            float a = g_Sx[l * NPTS + i];
            float c = g_Sy[l * NPTS + i];
            b = fmaf(a, c, b);
            tx += a; ty += c;
        }
        sB[tid] = b; sTx[tid] = tx; sTy[tid] = ty;
        __syncthreads();
        for (int s = 256; s > 0; s >>= 1) {
            if (tid < s) { sB[tid] += sB[tid + s]; sTx[tid] += sTx[tid + s]; sTy[tid] += sTy[tid + s]; }
            __syncthreads();
        }
        if (tid == 0)
            total += g_A[l] - 2.f * sB[0] / n + (sTx[0] * sTy[0]) / (n * n);
        __syncthreads();
    }
    if (tid == 0)
        out[0] = total / ((n - 1.f) * (n - 1.f));
}

// ---------------------------------------------------------------------------
extern "C" void kernel_launch(void* const* d_in, const int* in_sizes, int n_in,
                              void* d_out, int out_size) {
    const float* X = (const float*)d_in[0];
    const float* Y = (const float*)d_in[1];
    float* out = (float*)d_out;

    cudaFuncSetAttribute(hsic_main_kernel,
                         cudaFuncAttributeMaxDynamicSharedMemorySize, SMEM_BYTES);

    hsic_zero_kernel<<<(LSTEPS * NPTS + 255) / 256, 256>>>();
    hsic_transpose_kernel<<<dim3(NPTS / 4, 2), 256>>>(X, Y);
    hsic_main_kernel<<<dim3(NTILES, LSTEPS), 256, SMEM_BYTES>>>();
    hsic_finalize_kernel<<<1, 512>>>(out);
}

// round 2
// speedup vs baseline: 1.3045x; 1.3045x over previous
#include <cuda_runtime.h>
#include <cstdint>

// Problem: X (4096,64,16) fp32, Y (4096,64,16) fp32 -> scalar HSIC sum over 16 timesteps.
#define NPTS 4096
#define DDIM 64
#define LSTEPS 16
#define BT 128
#define NT (NPTS / BT)                    // 32
#define NTILES (NT * (NT + 1) / 2)        // 528 upper-tri tiles
#define SP 132                            // smem row stride in float2 (ull) units
#define TILE_ULL (DDIM * SP)
#define TILE_BYTES (TILE_ULL * 8)         // 67584
#define SMEM_BYTES (2 * TILE_BYTES)       // 135168
#define LOG2E 1.4426950408889634f

typedef unsigned long long ull;

// ---- device scratch (no cudaMalloc allowed) ----
__device__ ull   g_XYt[LSTEPS * DDIM * NPTS];  // [l][d][n] packed (x,y) fp32x2 : 32 MB
__device__ ull   g_C2[LSTEPS * NPTS];          // packed (-0.5*log2e*|x|^2, -0.5*log2e*|y|^2)
__device__ float2 g_S2[LSTEPS * NPTS];         // packed row sums (Sx, Sy)
__device__ float g_A[LSTEPS];
__device__ float g_R[LSTEPS];

// ---- fp32x2 / ptx helpers ----
__device__ __forceinline__ ull pack2(float x, float y) {
    ull r; asm("mov.b64 %0, {%1, %2};" : "=l"(r) : "f"(x), "f"(y)); return r;
}
__device__ __forceinline__ void unpack2(ull v, float& x, float& y) {
    asm("mov.b64 {%0, %1}, %2;" : "=f"(x), "=f"(y) : "l"(v));
}
__device__ __forceinline__ ull ffma2(ull a, ull b, ull c) {
    ull d; asm("fma.rn.f32x2 %0, %1, %2, %3;" : "=l"(d) : "l"(a), "l"(b), "l"(c)); return d;
}
__device__ __forceinline__ ull fadd2(ull a, ull b) {
    ull d; asm("add.rn.f32x2 %0, %1, %2;" : "=l"(d) : "l"(a), "l"(b)); return d;
}
__device__ __forceinline__ float ex2f(float x) {
    float r; asm("ex2.approx.f32 %0, %1;" : "=f"(r) : "f"(x)); return r;
}
__device__ __forceinline__ void lds2(ull& x, ull& y, uint32_t a) {
    asm("ld.shared.v2.b64 {%0, %1}, [%2];" : "=l"(x), "=l"(y) : "r"(a));
}
__device__ __forceinline__ ull lds1(uint32_t a) {
    ull x; asm("ld.shared.b64 %0, [%1];" : "=l"(x) : "r"(a)); return x;
}
__device__ __forceinline__ void cp16(uint32_t dst, const void* src) {
    asm volatile("cp.async.ca.shared.global [%0], [%1], 16;" :: "r"(dst), "l"(src));
}

// ---------------------------------------------------------------------------
__global__ void hsic_zero_kernel() {
    int i = blockIdx.x * 256 + threadIdx.x;
    if (i < LSTEPS * NPTS) g_S2[i] = make_float2(0.f, 0.f);
    if (i < LSTEPS) g_A[i] = 0.f;
}

// Transpose (N,D,L)x2 -> interleaved (L,D,N) float2 + packed exp2 constants.
__global__ void hsic_transpose_kernel(const float* __restrict__ X,
                                      const float* __restrict__ Y) {
    int n0 = blockIdx.x * 4;
    __shared__ float sx[4 * 16 * 65], sy[4 * 16 * 65];
    const int tid = threadIdx.x;
    #pragma unroll
    for (int it = 0; it < 16; it++) {
        int idx = it * 256 + tid;              // 0..4095
        int n = idx >> 10;
        int r = idx & 1023;                    // d*16 + l
        int d = r >> 4, l = r & 15;
        sx[n * 1040 + l * 65 + d] = X[(size_t)(n0 + n) * 1024 + r];
        sy[n * 1040 + l * 65 + d] = Y[(size_t)(n0 + n) * 1024 + r];
    }
    __syncthreads();
    #pragma unroll
    for (int it = 0; it < 16; it++) {
        int idx = it * 256 + tid;              // 0..4095
        int n = idx & 3;
        int d = (idx >> 2) & 63;
        int l = idx >> 8;
        float xv = sx[n * 1040 + l * 65 + d];
        float yv = sy[n * 1040 + l * 65 + d];
        g_XYt[((size_t)l * DDIM + d) * NPTS + n0 + n] = pack2(xv, yv);
    }
    if (tid < 64) {
        int n = tid >> 4, l = tid & 15;
        float qx = 0.f, qy = 0.f;
        #pragma unroll
        for (int d = 0; d < DDIM; d++) {
            float vx = sx[n * 1040 + l * 65 + d];
            float vy = sy[n * 1040 + l * 65 + d];
            qx = fmaf(vx, vx, qx);
            qy = fmaf(vy, vy, qy);
        }
        g_C2[l * NPTS + n0 + n] = pack2(-0.5f * LOG2E * qx, -0.5f * LOG2E * qy);
    }
}

// ---------------------------------------------------------------------------
// Main fused kernel: one block = one (l, ti<=tj) 128x128 pair tile.
// fp32x2 packs the X-Gram and Y-Gram into one FFMA2 stream (2x fp32 rate).
// ---------------------------------------------------------------------------
__global__ void __launch_bounds__(256, 1) hsic_main_kernel() {
    const int l = blockIdx.y;
    int t = blockIdx.x, ti = 0;
    while (t >= NT - ti) { t -= NT - ti; ti++; }
    const int tj = ti + t;
    const bool diag = (ti == tj);
    const int I = ti * BT, J = tj * BT;

    extern __shared__ ull smem[];
    __shared__ float sdot[8];
    uint32_t sb;
    asm("{ .reg .u64 t0; cvta.to.shared.u64 t0, %1; cvt.u32.u64 %0, t0; }"
        : "=r"(sb) : "l"(smem));

    const int tid = threadIdx.x;
    const ull* gsrc = g_XYt + (size_t)l * DDIM * NPTS;

    // ---- cp.async fill, two k-halves (double-buffered against compute) ----
    #pragma unroll
    for (int st = 0; st < 2; st++) {
        #pragma unroll
        for (int it = 0; it < 16; it++) {
            int c = it * 256 + tid;            // 0..4095
            int tile = c >> 11;                // 0 = i-side, 1 = j-side
            int rem = c & 2047;
            int kl = rem >> 6;                 // 0..31
            int m = (rem & 63) * 2;
            int k = st * 32 + kl;
            int base = tile ? J : I;
            const ull* src = gsrc + (size_t)k * NPTS + base + m;
            uint32_t dst = sb + tile * TILE_BYTES + (uint32_t)((k * SP + m) * 8);
            cp16(dst, src);
        }
        asm volatile("cp.async.commit_group;");
    }

    const int mb = (tid >> 4) << 3;            // 8 contiguous rows
    const int nb = tid & 15;                   // 8 stride-16 cols: nb + 16q
    ull acc[64];
    #pragma unroll
    for (int i = 0; i < 64; i++) acc[i] = 0ull;

    asm volatile("cp.async.wait_group 1;");
    __syncthreads();

    #pragma unroll 1
    for (int half = 0; half < 2; half++) {
        const int k0 = half * 32;
        #pragma unroll 4
        for (int kk = 0; kk < 32; kk++) {
            int k = k0 + kk;
            uint32_t ai = sb + (uint32_t)((k * SP + mb) * 8);
            uint32_t bj = sb + TILE_BYTES + (uint32_t)((k * SP + nb) * 8);
            ull a[8], b[8];
            lds2(a[0], a[1], ai);
            lds2(a[2], a[3], ai + 16);
            lds2(a[4], a[5], ai + 32);
            lds2(a[6], a[7], ai + 48);
            #pragma unroll
            for (int q = 0; q < 8; q++) b[q] = lds1(bj + q * 128);
            #pragma unroll
            for (int m = 0; m < 8; m++)
                #pragma unroll
                for (int q = 0; q < 8; q++)
                    acc[m * 8 + q] = ffma2(a[m], b[q], acc[m * 8 + q]);
        }
        if (half == 0) {
            asm volatile("cp.async.wait_group 0;");
            __syncthreads();
        }
    }

    // ---- epilogue: Kx = 2^(log2e*dotx + ci.x + cj.x), same for y, reductions ----
    ull ci2[8], cj2[8];
    #pragma unroll
    for (int r = 0; r < 8; r++) {
        ci2[r] = g_C2[l * NPTS + I + mb + r];
        cj2[r] = g_C2[l * NPTS + J + nb + 16 * r];
    }
    const ull L2E2 = pack2(LOG2E, LOG2E);
    float dotp = 0.f;
    ull rs2[8], cs2[8];
    #pragma unroll
    for (int r = 0; r < 8; r++) { rs2[r] = 0ull; cs2[r] = 0ull; }

    #pragma unroll
    for (int m = 0; m < 8; m++) {
        #pragma unroll
        for (int q = 0; q < 8; q++) {
            ull e2 = ffma2(acc[m * 8 + q], L2E2, fadd2(ci2[m], cj2[q]));
            float ex, ey;
            unpack2(e2, ex, ey);
            float kx = ex2f(ex);
            float ky = ex2f(ey);
            dotp = fmaf(kx, ky, dotp);
            ull k2 = pack2(kx, ky);
            rs2[m] = fadd2(rs2[m], k2);
            cs2[q] = fadd2(cs2[q], k2);
        }
    }

    // row sums: reduce over the 16 threads of a tile-row (contiguous lanes)
    #pragma unroll
    for (int r = 0; r < 8; r++) {
        float vx, vy;
        unpack2(rs2[r], vx, vy);
        #pragma unroll
        for (int o = 8; o > 0; o >>= 1) {
            vx += __shfl_xor_sync(0xffffffffu, vx, o);
            vy += __shfl_xor_sync(0xffffffffu, vy, o);
        }
        if ((tid & 15) == 0) {
            atomicAdd(&g_S2[l * NPTS + I + mb + r].x, vx);
            atomicAdd(&g_S2[l * NPTS + I + mb + r].y, vy);
        }
    }

    // tile dot: warp reduce
    float v = dotp;
    #pragma unroll
    for (int o = 16; o > 0; o >>= 1) v += __shfl_xor_sync(0xffffffffu, v, o);

    __syncthreads();   // done reading tiles; reuse smem for column staging

    ull* red = smem;   // [128][17] packed col partials
    const int tym = tid >> 4;
    #pragma unroll
    for (int q = 0; q < 8; q++)
        red[(nb + 16 * q) * 17 + tym] = cs2[q];
    if ((tid & 31) == 0) sdot[tid >> 5] = v;
    __syncthreads();

    if (tid == 0) {
        float s = 0.f;
        #pragma unroll
        for (int w = 0; w < 8; w++) s += sdot[w];
        atomicAdd(&g_A[l], diag ? s : 2.f * s);
    }
    if (tid < 128 && !diag) {
        ull s2 = 0ull;
        #pragma unroll
        for (int q = 0; q < 16; q++) s2 = fadd2(s2, red[tid * 17 + q]);
        float sx, sy;
        unpack2(s2, sx, sy);
        atomicAdd(&g_S2[l * NPTS + J + tid].x, sx);
        atomicAdd(&g_S2[l * NPTS + J + tid].y, sy);
    }
}

// ---------------------------------------------------------------------------
// Per-timestep closed form: R_l = A_l - (2/n) sum Sx*Sy + (sum Sx)(sum Sy)/n^2
__global__ void hsic_reduce_kernel() {
    const int l = blockIdx.x;
    const int tid = threadIdx.x;
    __shared__ float sB[256], sTx[256], sTy[256];
    float b = 0.f, tx = 0.f, ty = 0.f;
    for (int i = tid; i < NPTS; i += 256) {
        float2 s = g_S2[l * NPTS + i];
        b = fmaf(s.x, s.y, b);
        tx += s.x; ty += s.y;
    }
    sB[tid] = b; sTx[tid] = tx; sTy[tid] = ty;
    __syncthreads();
    for (int s = 128; s > 0; s >>= 1) {
        if (tid < s) { sB[tid] += sB[tid + s]; sTx[tid] += sTx[tid + s]; sTy[tid] += sTy[tid + s]; }
        __syncthreads();
    }
    if (tid == 0) {
        const float n = (float)NPTS;
        g_R[l] = g_A[l] - 2.f * sB[0] / n + sTx[0] * sTy[0] / (n * n);
    }
}

__global__ void hsic_final_kernel(float* __restrict__ out) {
    if (threadIdx.x == 0) {
        float t = 0.f;
        #pragma unroll
        for (int l = 0; l < LSTEPS; l++) t += g_R[l];
        const float n = (float)NPTS;
        out[0] = t / ((n - 1.f) * (n - 1.f));
    }
}

// ---------------------------------------------------------------------------
extern "C" void kernel_launch(void* const* d_in, const int* in_sizes, int n_in,
                              void* d_out, int out_size) {
    const float* X = (const float*)d_in[0];
    const float* Y = (const float*)d_in[1];
    float* out = (float*)d_out;

    cudaFuncSetAttribute(hsic_main_kernel,
                         cudaFuncAttributeMaxDynamicSharedMemorySize, SMEM_BYTES);

    hsic_zero_kernel<<<(LSTEPS * NPTS + 255) / 256, 256>>>();
    hsic_transpose_kernel<<<NPTS / 4, 256>>>(X, Y);
    hsic_main_kernel<<<dim3(NTILES, LSTEPS), 256, SMEM_BYTES>>>();
    hsic_reduce_kernel<<<LSTEPS, 256>>>();
    hsic_final_kernel<<<1, 32>>>(out);
}